// round 2
// baseline (speedup 1.0000x reference)
#include <cuda_runtime.h>

#define N_PTS   800000
#define B_SEG   16
#define PTS     50000
#define C_IN    32
#define C_HID   16
#define EPS_BN  1e-5f
#define EPS_NRM 1e-12f

#define BPS     32                         // blocks per segment in pass2
#define CHUNK   ((PTS + BPS - 1) / BPS)    // 1563

// ---------------- device scratch (allocation-free; zeroed every launch) ----
__device__ float g_sum_h [C_HID];
__device__ float g_sum_h2[C_HID];
__device__ float g_W1f   [C_HID * C_IN];
__device__ float g_b1f   [C_HID];
__device__ float g_sum_a;
__device__ float g_sum_a2;
__device__ float g_seg_xa[B_SEG][C_IN];
__device__ float g_seg_x [B_SEG][C_IN];

// ---------------------------------------------------------------- zero ----
__global__ void zero_kernel() {
    int t = threadIdx.x;
    for (int i = t; i < C_HID; i += blockDim.x) { g_sum_h[i] = 0.f; g_sum_h2[i] = 0.f; }
    if (t == 0) { g_sum_a = 0.f; g_sum_a2 = 0.f; }
    for (int i = t; i < B_SEG * C_IN; i += blockDim.x) {
        ((float*)g_seg_xa)[i] = 0.f;
        ((float*)g_seg_x )[i] = 0.f;
    }
}

// ------------------------------------------------- pass1: Sum h, Sum h^2 --
__global__ void __launch_bounds__(256)
pass1_kernel(const float* __restrict__ x,
             const float* __restrict__ W1,
             const float* __restrict__ b1) {
    __shared__ float sW[C_HID * C_IN];
    __shared__ float sb[C_HID];
    __shared__ float bacc[2 * C_HID];
    int tid = threadIdx.x;
    for (int i = tid; i < C_HID * C_IN; i += 256) sW[i] = W1[i];
    if (tid < C_HID)     sb[tid]   = b1[tid];
    if (tid < 2 * C_HID) bacc[tid] = 0.f;
    __syncthreads();

    float sh[C_HID], sh2[C_HID];
#pragma unroll
    for (int j = 0; j < C_HID; j++) { sh[j] = 0.f; sh2[j] = 0.f; }

    int stride = gridDim.x * blockDim.x;
    for (int i = blockIdx.x * blockDim.x + tid; i < N_PTS; i += stride) {
        const float4* xv = (const float4*)(x + (size_t)i * C_IN);
        float xr[C_IN];
#pragma unroll
        for (int q = 0; q < 8; q++) {
            float4 v = xv[q];
            xr[4*q+0] = v.x; xr[4*q+1] = v.y; xr[4*q+2] = v.z; xr[4*q+3] = v.w;
        }
#pragma unroll
        for (int j = 0; j < C_HID; j++) {
            float s = sb[j];
#pragma unroll
            for (int c = 0; c < C_IN; c++) s = fmaf(xr[c], sW[j * C_IN + c], s);
            sh[j]  += s;
            sh2[j] = fmaf(s, s, sh2[j]);
        }
    }

    // warp butterfly reduce
#pragma unroll
    for (int j = 0; j < C_HID; j++) {
#pragma unroll
        for (int o = 16; o > 0; o >>= 1) {
            sh [j] += __shfl_xor_sync(0xffffffffu, sh [j], o);
            sh2[j] += __shfl_xor_sync(0xffffffffu, sh2[j], o);
        }
    }
    if ((tid & 31) == 0) {
#pragma unroll
        for (int j = 0; j < C_HID; j++) {
            atomicAdd(&bacc[j],         sh [j]);
            atomicAdd(&bacc[C_HID + j], sh2[j]);
        }
    }
    __syncthreads();
    if (tid < C_HID) {
        atomicAdd(&g_sum_h [tid], bacc[tid]);
        atomicAdd(&g_sum_h2[tid], bacc[C_HID + tid]);
    }
}

// -------------------------------------- fold BN1 affine into W1', b1' -----
__global__ void fold_kernel(const float* __restrict__ W1,
                            const float* __restrict__ b1,
                            const float* __restrict__ gamma1,
                            const float* __restrict__ beta1) {
    int t = threadIdx.x;  // 512
    __shared__ float sInv[C_HID];
    if (t < C_HID) {
        float m   = g_sum_h [t] * (1.f / N_PTS);
        float v   = g_sum_h2[t] * (1.f / N_PTS) - m * m;
        float inv = rsqrtf(v + EPS_BN) * gamma1[t];
        sInv[t]   = inv;
        g_b1f[t]  = (b1[t] - m) * inv + beta1[t];
    }
    __syncthreads();
    if (t < C_HID * C_IN) {
        int j = t / C_IN;
        g_W1f[t] = W1[t] * sInv[j];
    }
}

// ---- pass2: a_pre stats + per-segment Sum(x*a_pre), Sum(x) ----------------
__global__ void __launch_bounds__(256)
pass2_kernel(const float* __restrict__ x,
             const float* __restrict__ W2,
             const float* __restrict__ b2) {
    __shared__ float sW[C_HID * C_IN];
    __shared__ float sb[C_HID];
    __shared__ float sw2[C_HID];
    __shared__ float sacc[2 * C_IN + 2];
    int tid = threadIdx.x;
    for (int i = tid; i < C_HID * C_IN; i += 256) sW[i] = g_W1f[i];
    if (tid < C_HID) { sb[tid] = g_b1f[tid]; sw2[tid] = W2[tid]; }
    if (tid < 2 * C_IN + 2) sacc[tid] = 0.f;
    __syncthreads();

    float b20 = b2[0];
    int seg   = blockIdx.x / BPS;
    int blk   = blockIdx.x % BPS;
    int start = seg * PTS + blk * CHUNK;
    int end   = min(seg * PTS + PTS, start + CHUNK);

    float axa[C_IN], ax[C_IN];
#pragma unroll
    for (int c = 0; c < C_IN; c++) { axa[c] = 0.f; ax[c] = 0.f; }
    float sa = 0.f, sa2 = 0.f;

    for (int i = start + tid; i < end; i += 256) {
        const float4* xv = (const float4*)(x + (size_t)i * C_IN);
        float xr[C_IN];
#pragma unroll
        for (int q = 0; q < 8; q++) {
            float4 v = xv[q];
            xr[4*q+0] = v.x; xr[4*q+1] = v.y; xr[4*q+2] = v.z; xr[4*q+3] = v.w;
        }
        float a = b20;
#pragma unroll
        for (int j = 0; j < C_HID; j++) {
            float s = sb[j];
#pragma unroll
            for (int c = 0; c < C_IN; c++) s = fmaf(xr[c], sW[j * C_IN + c], s);
            a = fmaf(fmaxf(s, 0.f), sw2[j], a);
        }
        sa  += a;
        sa2 = fmaf(a, a, sa2);
#pragma unroll
        for (int c = 0; c < C_IN; c++) {
            axa[c] = fmaf(xr[c], a, axa[c]);
            ax [c] += xr[c];
        }
    }

    // warp butterfly reduce (66 values)
#pragma unroll
    for (int o = 16; o > 0; o >>= 1) {
#pragma unroll
        for (int c = 0; c < C_IN; c++) {
            axa[c] += __shfl_xor_sync(0xffffffffu, axa[c], o);
            ax [c] += __shfl_xor_sync(0xffffffffu, ax [c], o);
        }
        sa  += __shfl_xor_sync(0xffffffffu, sa,  o);
        sa2 += __shfl_xor_sync(0xffffffffu, sa2, o);
    }
    if ((tid & 31) == 0) {
#pragma unroll
        for (int c = 0; c < C_IN; c++) {
            atomicAdd(&sacc[c],        axa[c]);
            atomicAdd(&sacc[C_IN + c], ax [c]);
        }
        atomicAdd(&sacc[2 * C_IN],     sa);
        atomicAdd(&sacc[2 * C_IN + 1], sa2);
    }
    __syncthreads();
    if (tid < C_IN) {
        atomicAdd(&g_seg_xa[seg][tid], sacc[tid]);
        atomicAdd(&g_seg_x [seg][tid], sacc[C_IN + tid]);
    }
    if (tid == 2 * C_IN)     atomicAdd(&g_sum_a,  sacc[2 * C_IN]);
    if (tid == 2 * C_IN + 1) atomicAdd(&g_sum_a2, sacc[2 * C_IN + 1]);
}

// --------------------------------------------------------- finalize -------
__global__ void finalize_kernel(const float* __restrict__ gamma2,
                                const float* __restrict__ beta2,
                                const int*   __restrict__ length,
                                float*       __restrict__ out) {
    int t = threadIdx.x;  // 512 = 16*32, one warp per segment
    float m     = g_sum_a  * (1.f / N_PTS);
    float v     = g_sum_a2 * (1.f / N_PTS) - m * m;
    float alpha = rsqrtf(v + EPS_BN) * gamma2[0];
    float betaC = beta2[0] - m * alpha;

    int b = t >> 5, c = t & 31;
    float cnt = (float)length[b];
    float val = (alpha * g_seg_xa[b][c] + betaC * g_seg_x[b][c]) / cnt;

    float sq = val * val;
#pragma unroll
    for (int o = 16; o > 0; o >>= 1) sq += __shfl_xor_sync(0xffffffffu, sq, o);
    float nrm = sqrtf(sq);
    out[t] = val / fmaxf(nrm, EPS_NRM);
}

// ---------------------------------------------------------------- launch --
extern "C" void kernel_launch(void* const* d_in, const int* in_sizes, int n_in,
                              void* d_out, int out_size) {
    const float* x      = (const float*)d_in[0];
    const float* W1     = (const float*)d_in[1];
    const float* b1     = (const float*)d_in[2];
    const float* gamma1 = (const float*)d_in[3];
    const float* beta1  = (const float*)d_in[4];
    const float* W2     = (const float*)d_in[5];
    const float* b2     = (const float*)d_in[6];
    const float* gamma2 = (const float*)d_in[7];
    const float* beta2  = (const float*)d_in[8];
    // d_in[9] = seg_ids (contiguous, derivable as i / PTS), d_in[10] = length
    const int* length   = (const int*)d_in[10];
    float* out          = (float*)d_out;

    zero_kernel<<<1, 256>>>();
    pass1_kernel<<<592, 256>>>(x, W1, b1);
    fold_kernel<<<1, 512>>>(W1, b1, gamma1, beta1);
    pass2_kernel<<<B_SEG * BPS, 256>>>(x, W2, b2);
    finalize_kernel<<<1, 512>>>(gamma2, beta2, length, out);
}

// round 4
// speedup vs baseline: 5.2736x; 5.2736x over previous
#include <cuda_runtime.h>

#define N_PTS   800000
#define B_SEG   16
#define PTS     50000
#define C_IN    32
#define C_HID   16
#define EPS_BN  1e-5f
#define EPS_NRM 1e-12f

#define GRID1   592
#define CHUNK1  ((N_PTS + GRID1 - 1) / GRID1)   // 1352

#define BPS     32                               // blocks per segment, pass2
#define CHUNK2  ((PTS + BPS - 1) / BPS)          // 1563
#define TP      128                              // pass2 tile (points)

#define WPAD    36                               // padded W row stride (floats)

// ---------------- device scratch (allocation-free; zeroed every launch) ----
__device__ float g_sum_h [C_HID];
__device__ float g_sum_h2[C_HID];
__device__ float g_W1f   [C_HID * C_IN];
__device__ float g_b1f   [C_HID];
__device__ float g_sum_a;
__device__ float g_sum_a2;
__device__ float g_seg_xa[B_SEG][C_IN];
__device__ float g_seg_x [B_SEG][C_IN];

// ---------------------------------------------------------------- zero ----
__global__ void zero_kernel() {
    int t = threadIdx.x;
    for (int i = t; i < C_HID; i += blockDim.x) { g_sum_h[i] = 0.f; g_sum_h2[i] = 0.f; }
    if (t == 0) { g_sum_a = 0.f; g_sum_a2 = 0.f; }
    for (int i = t; i < B_SEG * C_IN; i += blockDim.x) {
        ((float*)g_seg_xa)[i] = 0.f;
        ((float*)g_seg_x )[i] = 0.f;
    }
}

// ------------------------------------------------- pass1: Sum h, Sum h^2 --
// thread = (point-lane pl = tid>>4, channel j = tid&15). ~20 live registers.
__global__ void __launch_bounds__(256)
pass1_kernel(const float* __restrict__ x,
             const float* __restrict__ W1,
             const float* __restrict__ b1) {
    __shared__ __align__(16) float sW[C_HID * WPAD];
    __shared__ float sb[C_HID];
    __shared__ float red1[8 * C_HID];
    __shared__ float red2[8 * C_HID];
    int tid = threadIdx.x;
    for (int idx = tid; idx < C_HID * C_IN; idx += 256)
        sW[(idx >> 5) * WPAD + (idx & 31)] = W1[idx];
    if (tid < C_HID) sb[tid] = b1[tid];
    __syncthreads();

    int j  = tid & 15;
    int pl = tid >> 4;
    const float* wrow = &sW[j * WPAD];
    float bj = sb[j];

    int start = blockIdx.x * CHUNK1;
    int end   = min(N_PTS, start + CHUNK1);

    float sh = 0.f, sh2 = 0.f;
    for (int i = start + pl; i < end; i += 16) {
        const float4* xv = (const float4*)(x + (size_t)i * C_IN);
        float s = bj;
#pragma unroll
        for (int q = 0; q < 8; q++) {
            float4 v = xv[q];
            float4 w = *(const float4*)(wrow + 4 * q);
            s = fmaf(v.x, w.x, s); s = fmaf(v.y, w.y, s);
            s = fmaf(v.z, w.z, s); s = fmaf(v.w, w.w, s);
        }
        sh  += s;
        sh2  = fmaf(s, s, sh2);
    }

    // combine the two point-lanes within each warp (lane ^ 16, same j).
    // Loop above has NO warp syncs, so divergent trip counts are safe here.
    sh  += __shfl_xor_sync(0xffffffffu, sh,  16);
    sh2 += __shfl_xor_sync(0xffffffffu, sh2, 16);
    int lane = tid & 31, w = tid >> 5;
    if (lane < 16) { red1[w * 16 + lane] = sh; red2[w * 16 + lane] = sh2; }
    __syncthreads();
    if (tid < C_HID) {
        float a = 0.f, b = 0.f;
#pragma unroll
        for (int ww = 0; ww < 8; ww++) { a += red1[ww * 16 + tid]; b += red2[ww * 16 + tid]; }
        atomicAdd(&g_sum_h [tid], a);
        atomicAdd(&g_sum_h2[tid], b);
    }
}

// -------------------------------------- fold BN1 affine into W1', b1' -----
__global__ void fold_kernel(const float* __restrict__ W1,
                            const float* __restrict__ b1,
                            const float* __restrict__ gamma1,
                            const float* __restrict__ beta1) {
    int t = threadIdx.x;  // 512
    __shared__ float sInv[C_HID];
    if (t < C_HID) {
        float m   = g_sum_h [t] * (1.f / N_PTS);
        float v   = g_sum_h2[t] * (1.f / N_PTS) - m * m;
        float inv = rsqrtf(v + EPS_BN) * gamma1[t];
        sInv[t]   = inv;
        g_b1f[t]  = (b1[t] - m) * inv + beta1[t];
    }
    __syncthreads();
    if (t < C_HID * C_IN) {
        int j = t / C_IN;
        g_W1f[t] = W1[t] * sInv[j];
    }
}

// ---- pass2: a_pre stats + per-segment Sum(x*a_pre), Sum(x) ----------------
// Phase A: thread (pl, j) computes partial h_j, shfl-reduce over 16-group.
//          Trip count made BLOCK-UNIFORM (predicated tail) so the full-mask
//          shuffles can never deadlock.
// Phase B: thread (pg, c) accumulates axa/ax for one channel. ~25 registers.
__global__ void __launch_bounds__(256)
pass2_kernel(const float* __restrict__ x,
             const float* __restrict__ W2,
             const float* __restrict__ b2) {
    __shared__ __align__(16) float sW[C_HID * WPAD];
    __shared__ float sb1[C_HID];
    __shared__ float sw2[C_HID];
    __shared__ float as_[TP];
    __shared__ float r_axa[8 * C_IN];
    __shared__ float r_ax [8 * C_IN];
    __shared__ float r_sa [16];
    __shared__ float r_sa2[16];
    int tid = threadIdx.x;
    for (int idx = tid; idx < C_HID * C_IN; idx += 256)
        sW[(idx >> 5) * WPAD + (idx & 31)] = g_W1f[idx];
    if (tid < C_HID) { sb1[tid] = g_b1f[tid]; sw2[tid] = W2[tid]; }
    __syncthreads();

    int j  = tid & 15;
    int pl = tid >> 4;
    int c  = tid & 31;
    int pg = tid >> 5;
    const float* wrow = &sW[j * WPAD];
    float bj  = sb1[j];
    float w2j = sw2[j];
    float b20 = b2[0];

    int seg   = blockIdx.x / BPS;
    int blk   = blockIdx.x % BPS;
    int start = seg * PTS + blk * CHUNK2;
    int end   = min(seg * PTS + PTS, start + CHUNK2);

    float sa = 0.f, sa2 = 0.f, axa = 0.f, ax = 0.f;

    for (int ts = start; ts < end; ts += TP) {
        int tn = min(TP, end - ts);            // uniform across block

        // ---- Phase A: attention scalar per point (uniform trip count) ----
        int iters = (tn + 15) >> 4;
        for (int it = 0; it < iters; it++) {
            int p = pl + (it << 4);
            bool valid = p < tn;
            float r = 0.f;
            if (valid) {
                const float4* xv = (const float4*)(x + (size_t)(ts + p) * C_IN);
                float s = bj;
#pragma unroll
                for (int q = 0; q < 8; q++) {
                    float4 v = xv[q];
                    float4 w = *(const float4*)(wrow + 4 * q);
                    s = fmaf(v.x, w.x, s); s = fmaf(v.y, w.y, s);
                    s = fmaf(v.z, w.z, s); s = fmaf(v.w, w.w, s);
                }
                r = fmaxf(s, 0.f) * w2j;
            }
            // 16-lane group reduce over j (unconditional — all lanes present)
            r += __shfl_xor_sync(0xffffffffu, r, 8);
            r += __shfl_xor_sync(0xffffffffu, r, 4);
            r += __shfl_xor_sync(0xffffffffu, r, 2);
            r += __shfl_xor_sync(0xffffffffu, r, 1);
            if (valid && j == 0) {
                float a = r + b20;
                as_[p] = a;
                sa  += a;
                sa2  = fmaf(a, a, sa2);
            }
        }
        __syncthreads();

        // ---- Phase B: channel-split accumulation (x rows hot in L1) ----
        for (int p = pg; p < tn; p += 8) {
            float a  = as_[p];
            float xv = x[(size_t)(ts + p) * C_IN + c];
            axa = fmaf(xv, a, axa);
            ax += xv;
        }
        __syncthreads();
    }

    // ---- block reduction + global atomics ----
    r_axa[pg * C_IN + c] = axa;
    r_ax [pg * C_IN + c] = ax;
    if (j == 0) { r_sa[pl] = sa; r_sa2[pl] = sa2; }
    __syncthreads();
    if (tid < C_IN) {
        float A = 0.f, X = 0.f;
#pragma unroll
        for (int g = 0; g < 8; g++) { A += r_axa[g * C_IN + tid]; X += r_ax[g * C_IN + tid]; }
        atomicAdd(&g_seg_xa[seg][tid], A);
        atomicAdd(&g_seg_x [seg][tid], X);
    } else if (tid == C_IN) {
        float S = 0.f;
#pragma unroll
        for (int k = 0; k < 16; k++) S += r_sa[k];
        atomicAdd(&g_sum_a, S);
    } else if (tid == C_IN + 1) {
        float S = 0.f;
#pragma unroll
        for (int k = 0; k < 16; k++) S += r_sa2[k];
        atomicAdd(&g_sum_a2, S);
    }
}

// --------------------------------------------------------- finalize -------
__global__ void finalize_kernel(const float* __restrict__ gamma2,
                                const float* __restrict__ beta2,
                                const int*   __restrict__ length,
                                float*       __restrict__ out) {
    int t = threadIdx.x;  // 512 = 16*32, one warp per segment
    float m     = g_sum_a  * (1.f / N_PTS);
    float v     = g_sum_a2 * (1.f / N_PTS) - m * m;
    float alpha = rsqrtf(v + EPS_BN) * gamma2[0];
    float betaC = beta2[0] - m * alpha;

    int b = t >> 5, c = t & 31;
    float cnt = (float)length[b];
    float val = (alpha * g_seg_xa[b][c] + betaC * g_seg_x[b][c]) / cnt;

    float sq = val * val;
#pragma unroll
    for (int o = 16; o > 0; o >>= 1) sq += __shfl_xor_sync(0xffffffffu, sq, o);
    float nrm = sqrtf(sq);
    out[t] = val / fmaxf(nrm, EPS_NRM);
}

// ---------------------------------------------------------------- launch --
extern "C" void kernel_launch(void* const* d_in, const int* in_sizes, int n_in,
                              void* d_out, int out_size) {
    const float* x      = (const float*)d_in[0];
    const float* W1     = (const float*)d_in[1];
    const float* b1     = (const float*)d_in[2];
    const float* gamma1 = (const float*)d_in[3];
    const float* beta1  = (const float*)d_in[4];
    const float* W2     = (const float*)d_in[5];
    const float* b2     = (const float*)d_in[6];
    const float* gamma2 = (const float*)d_in[7];
    const float* beta2  = (const float*)d_in[8];
    const int* length   = (const int*)d_in[10];
    float* out          = (float*)d_out;

    zero_kernel<<<1, 256>>>();
    pass1_kernel<<<GRID1, 256>>>(x, W1, b1);
    fold_kernel<<<1, 512>>>(W1, b1, gamma1, beta1);
    pass2_kernel<<<B_SEG * BPS, 256>>>(x, W2, b2);
    finalize_kernel<<<1, 512>>>(gamma2, beta2, length, out);
}